// round 10
// baseline (speedup 1.0000x reference)
#include <cuda_runtime.h>
#include <cstdint>

#define BATCH   8
#define CH      512
#define HEADS   8
#define HD      64
#define GROUPS  32
#define CPG     16
#define NPIX    1024
#define EPS_GN  1e-6f
#define BK      16

typedef unsigned long long ull;

// -------- scratch: ~103 MB ----------
__device__ float g_qkv[BATCH * 3 * CH * NPIX];          // 48 MB
__device__ float g_ao [BATCH * CH * NPIX];              // 16 MB
__device__ float g_xn [BATCH * CH * NPIX];              // 16 MB
__device__ float g_vt [BATCH * HEADS * NPIX * HD];      // 16 MB Vt[bh][m][d]
__device__ float g_wtq[CH * 3 * CH];
__device__ float g_wtp[CH * CH];
__device__ float g_sc [BATCH * CH];
__device__ float g_tb [BATCH * CH];

// -------- helpers ----------
__device__ __forceinline__ ull pack2(float lo, float hi) {
    ull r; asm("mov.b64 %0, {%1, %2};" : "=l"(r) : "f"(lo), "f"(hi)); return r;
}
__device__ __forceinline__ void ffma2(ull& d, ull a, ull b) {
    asm("fma.rn.f32x2 %0, %1, %2, %0;" : "+l"(d) : "l"(a), "l"(b));
}
__device__ __forceinline__ void fadd2(ull& d, ull a) {
    asm("add.rn.f32x2 %0, %0, %1;" : "+l"(d) : "l"(a));
}
__device__ __forceinline__ float f2lo(ull v) { return __uint_as_float((unsigned)v); }
__device__ __forceinline__ float f2hi(ull v) { return __uint_as_float((unsigned)(v >> 32)); }
__device__ __forceinline__ uint32_t smem_u32(const void* p) {
    uint32_t a;
    asm("{ .reg .u64 t; cvta.to.shared.u64 t, %1; cvt.u32.u64 %0, t; }" : "=r"(a) : "l"(p));
    return a;
}
__device__ __forceinline__ void cpasync16(uint32_t dst, const void* src) {
    asm volatile("cp.async.ca.shared.global [%0], [%1], 16;" :: "r"(dst), "l"(src));
}
#define CP_COMMIT() asm volatile("cp.async.commit_group;" ::: "memory")
#define CP_WAIT1()  asm volatile("cp.async.wait_group 1;" ::: "memory")
#define CP_WAIT0()  asm volatile("cp.async.wait_group 0;" ::: "memory")

// =====================================================================
// 1) GroupNorm stats
// =====================================================================
__global__ void __launch_bounds__(256) gn_stats_kernel(
    const float* __restrict__ x,
    const float* __restrict__ gamma,
    const float* __restrict__ beta)
{
    const int bg = blockIdx.x;
    const int b  = bg / GROUPS;
    const int g  = bg % GROUPS;
    const int elems = CPG * NPIX;
    const float* xp = x + ((size_t)b * CH + g * CPG) * NPIX;

    float s = 0.f, sq = 0.f;
    for (int i = threadIdx.x; i < elems; i += 256) {
        float v = xp[i];
        s += v; sq += v * v;
    }
    #pragma unroll
    for (int o = 16; o > 0; o >>= 1) {
        s  += __shfl_xor_sync(0xffffffffu, s,  o);
        sq += __shfl_xor_sync(0xffffffffu, sq, o);
    }
    __shared__ float rs[8], rq[8];
    if ((threadIdx.x & 31) == 0) { rs[threadIdx.x >> 5] = s; rq[threadIdx.x >> 5] = sq; }
    __syncthreads();
    float S = 0.f, Q = 0.f;
    #pragma unroll
    for (int i = 0; i < 8; i++) { S += rs[i]; Q += rq[i]; }

    const float mean = S * (1.f / elems);
    const float var  = Q * (1.f / elems) - mean * mean;
    const float inv  = rsqrtf(var + EPS_GN);

    if (threadIdx.x < CPG) {
        const int ch = g * CPG + threadIdx.x;
        const float sc = inv * gamma[ch];
        g_sc[b * CH + ch] = sc;
        g_tb[b * CH + ch] = beta[ch] - mean * sc;
    }
}

// 1b) apply GN affine: xn = x*s + t
__global__ void __launch_bounds__(256) gn_apply_kernel(const float* __restrict__ x)
{
    const int i4 = blockIdx.x * 256 + threadIdx.x;
    const int e  = i4 * 4;
    const int b  = e >> 19;
    const int c  = (e >> 10) & (CH - 1);
    const float s = g_sc[b * CH + c];
    const float t = g_tb[b * CH + c];
    float4 v = *(const float4*)&x[e];
    v.x = v.x * s + t; v.y = v.y * s + t; v.z = v.z * s + t; v.w = v.w * s + t;
    *(float4*)&g_xn[e] = v;
}

// 1c) weight transpose: Wt[k][m] = W[m][k]
__global__ void __launch_bounds__(256) wtrans_kernel(
    const float* __restrict__ W, float* __restrict__ Wt, int M, int K)
{
    __shared__ float tile[32][33];
    const int k0 = blockIdx.x * 32, m0 = blockIdx.y * 32;
    const int tx = threadIdx.x & 31, ty = threadIdx.x >> 5;
    #pragma unroll
    for (int r = 0; r < 32; r += 8)
        tile[ty + r][tx] = W[(size_t)(m0 + ty + r) * K + k0 + tx];
    __syncthreads();
    #pragma unroll
    for (int r = 0; r < 32; r += 8)
        Wt[(size_t)(k0 + ty + r) * M + m0 + tx] = tile[tx][ty + r];
}

// 1d) V transpose: Vt[bh][m][d] = V[bh][d][m]
__global__ void __launch_bounds__(256) vtrans_kernel()
{
    __shared__ float tile[32][33];
    const int bh = blockIdx.z;
    const int b = bh >> 3, h = bh & 7;
    const float* V = g_qkv + ((size_t)b * 3 * CH + 2 * CH + h * HD) * NPIX;
    float* Vt = g_vt + (size_t)bh * NPIX * HD;
    const int m0 = blockIdx.x * 32;
    const int d0 = blockIdx.y * 32;
    const int tx = threadIdx.x & 31, ty = threadIdx.x >> 5;
    #pragma unroll
    for (int r = 0; r < 32; r += 8)
        tile[ty + r][tx] = V[(size_t)(d0 + ty + r) * NPIX + m0 + tx];
    __syncthreads();
    #pragma unroll
    for (int r = 0; r < 32; r += 8)
        Vt[(size_t)(m0 + ty + r) * HD + d0 + tx] = tile[tx][ty + r];
}

// =====================================================================
// 2) Unified 128-thread 8x16-microtile GEMM (cp.async double-buffered)
// =====================================================================
__global__ void __launch_bounds__(128) wg128_kernel(
    const float* __restrict__ At,     // [K][Mdim]
    const float* __restrict__ bias,
    const float* __restrict__ B,      // [batch][K][NPIX]
    const float* __restrict__ res,
    float* __restrict__ C,
    int Mdim, int Kdim)
{
    __shared__ __align__(16) float As[2][BK][128];
    __shared__ __align__(16) float Bs[2][BK][128];

    const int tid = threadIdx.x;
    const int ty = tid & 15, tx = tid >> 4;
    const int bz = blockIdx.z;
    const int o0 = blockIdx.y * 128, n0 = blockIdx.x * 128;

    const float* Ab = At + o0;
    const float* Bb = B + (size_t)bz * Kdim * NPIX + n0;
    const uint32_t asb = smem_u32(As);
    const uint32_t bsb = smem_u32(Bs);

    ull acc[8][8];
    #pragma unroll
    for (int i = 0; i < 8; i++)
        #pragma unroll
        for (int j = 0; j < 8; j++) acc[i][j] = 0ull;

    #pragma unroll
    for (int s = 0; s < 4; s++) {
        int sg = tid + s * 128, r = sg >> 5, c = (sg & 31) << 2;
        cpasync16(asb + (uint32_t)((r * 128 + c) * 4), Ab + (size_t)r * Mdim + c);
        cpasync16(bsb + (uint32_t)((r * 128 + c) * 4), Bb + (size_t)r * NPIX + c);
    }
    CP_COMMIT();

    const int nt = Kdim / BK;
    for (int t = 0; t < nt; t++) {
        const int buf = t & 1;
        if (t + 1 < nt) {
            const int k0 = (t + 1) * BK, nb = buf ^ 1;
            #pragma unroll
            for (int s = 0; s < 4; s++) {
                int sg = tid + s * 128, r = sg >> 5, c = (sg & 31) << 2;
                cpasync16(asb + (uint32_t)(((nb * BK + r) * 128 + c) * 4),
                          Ab + (size_t)(k0 + r) * Mdim + c);
                cpasync16(bsb + (uint32_t)(((nb * BK + r) * 128 + c) * 4),
                          Bb + (size_t)(k0 + r) * NPIX + c);
            }
            CP_COMMIT();
            CP_WAIT1();
        } else {
            CP_WAIT0();
        }
        __syncthreads();

        #pragma unroll
        for (int kk = 0; kk < BK; kk++) {
            float4 a0 = *(const float4*)&As[buf][kk][ty * 8];
            float4 a1 = *(const float4*)&As[buf][kk][ty * 8 + 4];
            ulonglong2 b01 = *(const ulonglong2*)&Bs[buf][kk][tx * 16];
            ulonglong2 b23 = *(const ulonglong2*)&Bs[buf][kk][tx * 16 + 4];
            ulonglong2 b45 = *(const ulonglong2*)&Bs[buf][kk][tx * 16 + 8];
            ulonglong2 b67 = *(const ulonglong2*)&Bs[buf][kk][tx * 16 + 12];
            ull ap[8] = { pack2(a0.x, a0.x), pack2(a0.y, a0.y),
                          pack2(a0.z, a0.z), pack2(a0.w, a0.w),
                          pack2(a1.x, a1.x), pack2(a1.y, a1.y),
                          pack2(a1.z, a1.z), pack2(a1.w, a1.w) };
            ull bp[8] = { b01.x, b01.y, b23.x, b23.y, b45.x, b45.y, b67.x, b67.y };
            #pragma unroll
            for (int i = 0; i < 8; i++)
                #pragma unroll
                for (int j = 0; j < 8; j++)
                    ffma2(acc[i][j], ap[i], bp[j]);
        }
        __syncthreads();
    }

    float* Cb = C + (size_t)bz * Mdim * NPIX;
    const float* Rb = res ? res + (size_t)bz * Mdim * NPIX : nullptr;
    #pragma unroll
    for (int i = 0; i < 8; i++) {
        const int o = o0 + ty * 8 + i;
        const float bv = bias[o];
        float* cp = &Cb[(size_t)o * NPIX + n0 + tx * 16];
        const float* rp = Rb ? &Rb[(size_t)o * NPIX + n0 + tx * 16] : nullptr;
        #pragma unroll
        for (int j2 = 0; j2 < 4; j2++) {
            float4 v = make_float4(f2lo(acc[i][2 * j2])     + bv,
                                   f2hi(acc[i][2 * j2])     + bv,
                                   f2lo(acc[i][2 * j2 + 1]) + bv,
                                   f2hi(acc[i][2 * j2 + 1]) + bv);
            if (rp) {
                float4 q = *(const float4*)(rp + j2 * 4);
                v.x += q.x; v.y += q.y; v.z += q.z; v.w += q.w;
            }
            *(float4*)(cp + j2 * 4) = v;
        }
    }
}

// =====================================================================
// 3) Fused attention: per CTA one (bh, 128-n block).
//    Loop m-tiles of 128: S=K^T Q -> exp -> smem; O += Vt^T S~.
//    l accumulated in phase-A epilogue; normalize at end.
//    smem: Q 32K | K x2 32K | V x2 32K | S 64K = 224 KB dynamic.
// =====================================================================
#define FA_SMEM (57344 * 4)

__global__ void __launch_bounds__(256, 1) fused_attn_kernel()
{
    extern __shared__ __align__(16) float smf[];
    float* Qs  = smf;              // [64][128]
    float* Ks0 = smf + 8192;       // [2][64][128]
    float* Vs0 = smf + 24576;      // [2][128][64]
    float* Ssm = smf + 40960;      // [128][128]

    const int tid = threadIdx.x;
    const int ty = tid & 15;       // n-group (8 cols at ty*8)
    const int tx = tid >> 4;       // phase A: m-group (8 rows); phase B: d-group (4 rows)
    const int n0 = blockIdx.x * 128;
    const int bh = blockIdx.y;
    const int b = bh >> 3, h = bh & 7;

    const float* qg = g_qkv + ((size_t)b * 3 * CH + h * HD) * NPIX;
    const float* kg = g_qkv + ((size_t)b * 3 * CH + CH + h * HD) * NPIX;
    const float* vtg = g_vt + (size_t)bh * NPIX * HD;

    const uint32_t qsb = smem_u32(Qs);
    const uint32_t ksb = smem_u32(Ks0);
    const uint32_t vsb = smem_u32(Vs0);

    auto load_K = [&](int mt, int buf) {
        #pragma unroll
        for (int s = 0; s < 8; s++) {
            int idx = tid + s * 256, r = idx >> 5, c = (idx & 31) << 2;
            cpasync16(ksb + (uint32_t)(buf * 32768 + (r * 128 + c) * 4),
                      kg + (size_t)r * NPIX + mt * 128 + c);
        }
    };
    auto load_V = [&](int mt, int buf) {
        #pragma unroll
        for (int s = 0; s < 8; s++) {
            int idx = tid + s * 256, r = idx >> 4, c = (idx & 15) << 2;
            cpasync16(vsb + (uint32_t)(buf * 32768 + (r * 64 + c) * 4),
                      vtg + (size_t)(mt * 128 + r) * HD + c);
        }
    };

    // prologue: Q (resident) + K0 + V0
    #pragma unroll
    for (int s = 0; s < 8; s++) {
        int idx = tid + s * 256, r = idx >> 5, c = (idx & 31) << 2;
        cpasync16(qsb + (uint32_t)((r * 128 + c) * 4), qg + (size_t)r * NPIX + n0 + c);
    }
    load_K(0, 0);
    load_V(0, 0);
    CP_COMMIT();

    ull acc_o[4][4];
    #pragma unroll
    for (int i = 0; i < 4; i++)
        #pragma unroll
        for (int j = 0; j < 4; j++) acc_o[i][j] = 0ull;
    ull ls[4] = {0ull, 0ull, 0ull, 0ull};

    const float scale = 0.125f;

    for (int t = 0; t < 8; t++) {
        const int buf = t & 1;
        if (t + 1 < 8) {
            load_K(t + 1, buf ^ 1);
            load_V(t + 1, buf ^ 1);
            CP_COMMIT();
            CP_WAIT1();
        } else {
            CP_WAIT0();
        }
        __syncthreads();   // K/V[buf] visible; also: everyone done with prev Ss

        // ---- Phase A: S = K^T Q (128m x 128n), microtile 8m x 8n ----
        const float* Ksb = Ks0 + buf * 8192;
        ull acc_s[8][4];
        #pragma unroll
        for (int i = 0; i < 8; i++)
            #pragma unroll
            for (int j = 0; j < 4; j++) acc_s[i][j] = 0ull;

        #pragma unroll 8
        for (int kk = 0; kk < 64; kk++) {
            float4 a0 = *(const float4*)(Ksb + kk * 128 + tx * 8);
            float4 a1 = *(const float4*)(Ksb + kk * 128 + tx * 8 + 4);
            ulonglong2 b01 = *(const ulonglong2*)(Qs + kk * 128 + ty * 8);
            ulonglong2 b23 = *(const ulonglong2*)(Qs + kk * 128 + ty * 8 + 4);
            ull ap[8] = { pack2(a0.x, a0.x), pack2(a0.y, a0.y),
                          pack2(a0.z, a0.z), pack2(a0.w, a0.w),
                          pack2(a1.x, a1.x), pack2(a1.y, a1.y),
                          pack2(a1.z, a1.z), pack2(a1.w, a1.w) };
            ull bp[4] = { b01.x, b01.y, b23.x, b23.y };
            #pragma unroll
            for (int i = 0; i < 8; i++)
                #pragma unroll
                for (int j = 0; j < 4; j++)
                    ffma2(acc_s[i][j], ap[i], bp[j]);
        }

        // ---- exp + stage to smem + l partials ----
        #pragma unroll
        for (int i = 0; i < 8; i++) {
            const int m = tx * 8 + i;
            float e0 = __expf(f2lo(acc_s[i][0]) * scale);
            float e1 = __expf(f2hi(acc_s[i][0]) * scale);
            float e2 = __expf(f2lo(acc_s[i][1]) * scale);
            float e3 = __expf(f2hi(acc_s[i][1]) * scale);
            float e4 = __expf(f2lo(acc_s[i][2]) * scale);
            float e5 = __expf(f2hi(acc_s[i][2]) * scale);
            float e6 = __expf(f2lo(acc_s[i][3]) * scale);
            float e7 = __expf(f2hi(acc_s[i][3]) * scale);
            fadd2(ls[0], pack2(e0, e1));
            fadd2(ls[1], pack2(e2, e3));
            fadd2(ls[2], pack2(e4, e5));
            fadd2(ls[3], pack2(e6, e7));
            float* srow = Ssm + m * 128 + ty * 8;
            *(float4*)(srow)     = make_float4(e0, e1, e2, e3);
            *(float4*)(srow + 4) = make_float4(e4, e5, e6, e7);
        }
        __syncthreads();   // Ss ready for all

        // ---- Phase B: O += Vt^T S~ (64d x 128n), microtile 4d x 8n ----
        const float* Vsb = Vs0 + buf * 8192;
        #pragma unroll 4
        for (int kk = 0; kk < 128; kk++) {
            float4 v0 = *(const float4*)(Vsb + kk * 64 + tx * 4);
            ulonglong2 s01 = *(const ulonglong2*)(Ssm + kk * 128 + ty * 8);
            ulonglong2 s23 = *(const ulonglong2*)(Ssm + kk * 128 + ty * 8 + 4);
            ull vd[4] = { pack2(v0.x, v0.x), pack2(v0.y, v0.y),
                          pack2(v0.z, v0.z), pack2(v0.w, v0.w) };
            ull sp[4] = { s01.x, s01.y, s23.x, s23.y };
            #pragma unroll
            for (int i = 0; i < 4; i++)
                #pragma unroll
                for (int j = 0; j < 4; j++)
                    ffma2(acc_o[i][j], vd[i], sp[j]);
        }
        __syncthreads();   // all done reading Ss / V[buf] before next prefetch/STS
    }

    // ---- l reduction across the 16 m-groups (reuse Ss as staging) ----
    float* lstage = Ssm;   // [16][128]
    {
        float* lp = lstage + tx * 128 + ty * 8;
        *(float4*)(lp)     = make_float4(f2lo(ls[0]), f2hi(ls[0]), f2lo(ls[1]), f2hi(ls[1]));
        *(float4*)(lp + 4) = make_float4(f2lo(ls[2]), f2hi(ls[2]), f2lo(ls[3]), f2hi(ls[3]));
    }
    __syncthreads();
    float4 la = make_float4(0.f, 0.f, 0.f, 0.f);
    float4 lb = make_float4(0.f, 0.f, 0.f, 0.f);
    #pragma unroll
    for (int g = 0; g < 16; g++) {
        float4 pa = *(const float4*)(lstage + g * 128 + ty * 8);
        float4 pb = *(const float4*)(lstage + g * 128 + ty * 8 + 4);
        la.x += pa.x; la.y += pa.y; la.z += pa.z; la.w += pa.w;
        lb.x += pb.x; lb.y += pb.y; lb.z += pb.z; lb.w += pb.w;
    }
    const float i0 = 1.f / la.x, i1 = 1.f / la.y, i2 = 1.f / la.z, i3 = 1.f / la.w;
    const float i4 = 1.f / lb.x, i5 = 1.f / lb.y, i6 = 1.f / lb.z, i7 = 1.f / lb.w;

    // ---- normalize + store O ----
    float* aob = g_ao + ((size_t)b * CH + h * HD) * NPIX + n0;
    #pragma unroll
    for (int i = 0; i < 4; i++) {
        const int d = tx * 4 + i;
        float4 r0 = make_float4(f2lo(acc_o[i][0]) * i0, f2hi(acc_o[i][0]) * i1,
                                f2lo(acc_o[i][1]) * i2, f2hi(acc_o[i][1]) * i3);
        float4 r1 = make_float4(f2lo(acc_o[i][2]) * i4, f2hi(acc_o[i][2]) * i5,
                                f2lo(acc_o[i][3]) * i6, f2hi(acc_o[i][3]) * i7);
        float* op = aob + (size_t)d * NPIX + ty * 8;
        *(float4*)(op)     = r0;
        *(float4*)(op + 4) = r1;
    }
}

// =====================================================================
// launcher
// =====================================================================
extern "C" void kernel_launch(void* const* d_in, const int* in_sizes, int n_in,
                              void* d_out, int out_size)
{
    const float* x      = (const float*)d_in[0];
    const float* norm_w = (const float*)d_in[1];
    const float* norm_b = (const float*)d_in[2];
    const float* qkv_w  = (const float*)d_in[3];
    const float* qkv_b  = (const float*)d_in[4];
    const float* proj_w = (const float*)d_in[5];
    const float* proj_b = (const float*)d_in[6];
    float* out = (float*)d_out;

    float *qkv_p, *ao_p, *xn_p, *wtq_p, *wtp_p;
    cudaGetSymbolAddress((void**)&qkv_p, g_qkv);
    cudaGetSymbolAddress((void**)&ao_p,  g_ao);
    cudaGetSymbolAddress((void**)&xn_p,  g_xn);
    cudaGetSymbolAddress((void**)&wtq_p, g_wtq);
    cudaGetSymbolAddress((void**)&wtp_p, g_wtp);

    cudaFuncSetAttribute(fused_attn_kernel,
                         cudaFuncAttributeMaxDynamicSharedMemorySize, FA_SMEM);

    // 1) GroupNorm + weight transposes
    gn_stats_kernel<<<BATCH * GROUPS, 256>>>(x, norm_w, norm_b);
    gn_apply_kernel<<<BATCH * CH * NPIX / 1024, 256>>>(x);
    {
        dim3 g1(CH / 32, 3 * CH / 32);
        wtrans_kernel<<<g1, 256>>>(qkv_w, wtq_p, 3 * CH, CH);
        dim3 g2(CH / 32, CH / 32);
        wtrans_kernel<<<g2, 256>>>(proj_w, wtp_p, CH, CH);
    }

    // 2) QKV projection: M=1536, K=512
    {
        dim3 grid(NPIX / 128, (3 * CH) / 128, BATCH);
        wg128_kernel<<<grid, 128>>>(wtq_p, qkv_b, xn_p, nullptr, qkv_p, 3 * CH, CH);
    }

    // 2b) transpose V for all heads
    {
        dim3 grid(NPIX / 32, HD / 32, BATCH * HEADS);
        vtrans_kernel<<<grid, 256>>>();
    }

    // 3) fused attention (QK -> exp -> AV -> normalize), one launch
    {
        dim3 grid(NPIX / 128, BATCH * HEADS);
        fused_attn_kernel<<<grid, 256, FA_SMEM>>>();
    }

    // 4) proj + bias + residual: M=512, K=512
    {
        dim3 grid(NPIX / 128, CH / 128, BATCH);
        wg128_kernel<<<grid, 128>>>(wtp_p, proj_b, ao_p, x, out, CH, CH);
    }
}